// round 1
// baseline (speedup 1.0000x reference)
#include <cuda_runtime.h>

typedef unsigned long long u64;

#define TT 512          // sequence length
#define HH 8            // hidden size
#define WPB 2           // warps per block
#define NTHR (WPB * 32)

#define LOG2E 1.4426950408889634f

// ---- packed f32x2 helpers (Blackwell sm_103a packed fp32 math) ----
static __device__ __forceinline__ u64 pk2(float lo, float hi) {
    u64 r; asm("mov.b64 %0, {%1,%2};" : "=l"(r) : "f"(lo), "f"(hi)); return r;
}
static __device__ __forceinline__ void upk2(u64 v, float& lo, float& hi) {
    asm("mov.b64 {%0,%1}, %2;" : "=f"(lo), "=f"(hi) : "l"(v));
}
static __device__ __forceinline__ u64 ffma2(u64 a, u64 b, u64 c) {
    u64 d; asm("fma.rn.f32x2 %0,%1,%2,%3;" : "=l"(d) : "l"(a), "l"(b), "l"(c)); return d;
}
static __device__ __forceinline__ u64 fmul2(u64 a, u64 b) {
    u64 d; asm("mul.rn.f32x2 %0,%1,%2;" : "=l"(d) : "l"(a), "l"(b)); return d;
}
static __device__ __forceinline__ u64 fadd2(u64 a, u64 b) {
    u64 d; asm("add.rn.f32x2 %0,%1,%2;" : "=l"(d) : "l"(a), "l"(b)); return d;
}
static __device__ __forceinline__ float ex2f(float x) {
    float y; asm("ex2.approx.f32 %0,%1;" : "=f"(y) : "f"(x)); return y;
}
static __device__ __forceinline__ float rcpf(float x) {
    float y; asm("rcp.approx.f32 %0,%1;" : "=f"(y) : "f"(x)); return y;
}

// Activation of a packed pair. Input g is the PRE-SCALED pre-activation:
//   sigmoid lanes: g = -z*log2e  -> sigma(z) = rcp(1 + 2^g)            (kA=+1, kB=0)
//   tanh lanes:    g = 2z*log2e  -> tanh(z)  = 1 - 2*rcp(1 + 2^g)     (kA=-2, kB=1)
// One MUFU.RCP serves BOTH halves via the reciprocal-of-product trick.
static __device__ __forceinline__ u64 act_pair(u64 g, float kA, float kB) {
    float a, b; upk2(g, a, b);
    a = fminf(a, 60.f);            // 2^60 keeps d0*d1 < 2^120 (no fp32 overflow)
    b = fminf(b, 60.f);
    float d0 = 1.f + ex2f(a);
    float d1 = 1.f + ex2f(b);
    float r  = rcpf(d0 * d1);
    float r0 = r * d1;             // = 1/d0
    float r1 = r * d0;             // = 1/d1
    return pk2(fmaf(kA, r0, kB), fmaf(kA, r1, kB));
}

// scalar tanh via ex2 (accurate): tanh(c) = 1 - 2/(1 + e^{2c})
static __device__ __forceinline__ float tanh_acc(float c) {
    float z = fminf(c * (2.f * LOG2E), 60.f);
    return fmaf(-2.f, rcpf(1.f + ex2f(z)), 1.f);
}

__global__ void __launch_bounds__(NTHR, 7)
lstm2_kernel(const float* __restrict__ x,
             const float* __restrict__ W_ih1, const float* __restrict__ W_hh1,
             const float* __restrict__ b_ih1, const float* __restrict__ b_hh1,
             const float* __restrict__ W_ih2, const float* __restrict__ W_hh2,
             const float* __restrict__ b_ih2, const float* __restrict__ b_hh2,
             const float* __restrict__ W_fc,  const float* __restrict__ b_fc,
             float* __restrict__ out, int B)
{
    // Per-warp scratch: 32 packed gate activations, 8 packed h per layer.
    __shared__ __align__(16) u64 sAct[WPB][32];
    __shared__ __align__(16) u64 sH1[WPB][8];
    __shared__ __align__(16) u64 sH2[WPB][8];

    const int lane = threadIdx.x & 31;
    const int wrp  = threadIdx.x >> 5;
    const int wg   = blockIdx.x * WPB + wrp;   // global warp id
    const int b0   = wg * 2;
    const int b1   = b0 + 1;
    if (b1 >= B) return;

    const int k8   = lane & 7;
    const int k8p8 = k8 + 8;

    // Gate type by row: 0-7 i(sig), 8-15 f(sig), 16-23 g(tanh), 24-31 o(sig)
    const bool isTanh = (lane >= 16 && lane < 24);
    const float pre = isTanh ? (2.f * LOG2E) : (-LOG2E);
    const float kA  = isTanh ? -2.f : 1.f;
    const float kB  = isTanh ?  1.f : 0.f;

    // ---- dup-packed, pre-scaled weights (resident in registers) ----
    u64 wx1 = pk2(W_ih1[lane] * pre, W_ih1[lane] * pre);
    float bs1 = (b_ih1[lane] + b_hh1[lane]) * pre;
    float bs2 = (b_ih2[lane] + b_hh2[lane]) * pre;
    u64 bb1 = pk2(bs1, bs1);
    u64 bb2 = pk2(bs2, bs2);
    u64 wh1[HH], wi2[HH], wh2[HH];
#pragma unroll
    for (int k = 0; k < HH; k++) {
        float a = W_hh1[lane * HH + k] * pre;  wh1[k] = pk2(a, a);
        float b = W_ih2[lane * HH + k] * pre;  wi2[k] = pk2(b, b);
        float c = W_hh2[lane * HH + k] * pre;  wh2[k] = pk2(c, c);
    }

    // ---- states ----
    const u64 z2 = pk2(0.f, 0.f);
    u64 h1v[HH], h2v[HH];
#pragma unroll
    for (int k = 0; k < HH; k++) { h1v[k] = z2; h2v[k] = z2; }
    u64 c1 = z2, c2 = z2;

    const float* xr0 = x + (size_t)b0 * TT;
    const float* xr1 = x + (size_t)b1 * TT;

    for (int tc = 0; tc < TT; tc += 32) {
        // 32 timesteps of x for both batches, coalesced, distributed via shfl
        float xa = xr0[tc + lane];
        float xb = xr1[tc + lane];

#pragma unroll 8
        for (int u = 0; u < 32; u++) {
            float x0 = __shfl_sync(0xffffffffu, xa, u);
            float x1 = __shfl_sync(0xffffffffu, xb, u);
            u64 xp = pk2(x0, x1);

            // ======== LAYER 1 gates: g = pre*(Wih*x + b + Whh@h1) ========
            u64 aE = ffma2(wx1, xp, bb1);
            u64 aO = fmul2(wh1[1], h1v[1]);
            aE = ffma2(wh1[0], h1v[0], aE);
            aO = ffma2(wh1[3], h1v[3], aO);
            aE = ffma2(wh1[2], h1v[2], aE);
            aO = ffma2(wh1[5], h1v[5], aO);
            aE = ffma2(wh1[4], h1v[4], aE);
            aO = ffma2(wh1[7], h1v[7], aO);
            aE = ffma2(wh1[6], h1v[6], aE);
            u64 a1 = act_pair(fadd2(aE, aO), kA, kB);

            sAct[wrp][lane] = a1;
            __syncwarp();
            u64 ip = sAct[wrp][k8];
            u64 fp = sAct[wrp][k8 + 8];
            u64 gp = sAct[wrp][k8 + 16];
            u64 op = sAct[wrp][k8 + 24];

            // c1 = f*c1 + i*g   (all lanes redundantly, index k8)
            c1 = ffma2(fp, c1, fmul2(ip, gp));

            // tanh(c1): de-dup across halves — each lane does ONE scalar
            float clo, chi; upk2(c1, clo, chi);
            float cs = (lane & 8) ? chi : clo;
            float tC = tanh_acc(cs);
            float tlo = __shfl_sync(0xffffffffu, tC, k8);
            float thi = __shfl_sync(0xffffffffu, tC, k8p8);
            u64 hp = fmul2(op, pk2(tlo, thi));

            if (lane < 8) sH1[wrp][lane] = hp;
            __syncwarp();
            {
                const ulonglong2* p = (const ulonglong2*)&sH1[wrp][0];
                ulonglong2 v0 = p[0], v1 = p[1], v2 = p[2], v3 = p[3];
                h1v[0] = v0.x; h1v[1] = v0.y; h1v[2] = v1.x; h1v[3] = v1.y;
                h1v[4] = v2.x; h1v[5] = v2.y; h1v[6] = v3.x; h1v[7] = v3.y;
            }

            // ======== LAYER 2 gates: g = pre*(Wih2@h1 + b + Whh2@h2) ========
            aE = ffma2(wi2[0], h1v[0], bb2);
            aO = fmul2(wi2[1], h1v[1]);
            aE = ffma2(wi2[2], h1v[2], aE);
            aO = ffma2(wi2[3], h1v[3], aO);
            aE = ffma2(wi2[4], h1v[4], aE);
            aO = ffma2(wi2[5], h1v[5], aO);
            aE = ffma2(wi2[6], h1v[6], aE);
            aO = ffma2(wi2[7], h1v[7], aO);
            aE = ffma2(wh2[0], h2v[0], aE);
            aO = ffma2(wh2[1], h2v[1], aO);
            aE = ffma2(wh2[2], h2v[2], aE);
            aO = ffma2(wh2[3], h2v[3], aO);
            aE = ffma2(wh2[4], h2v[4], aE);
            aO = ffma2(wh2[5], h2v[5], aO);
            aE = ffma2(wh2[6], h2v[6], aE);
            aO = ffma2(wh2[7], h2v[7], aO);
            u64 a2 = act_pair(fadd2(aE, aO), kA, kB);

            sAct[wrp][lane] = a2;
            __syncwarp();
            u64 ip2 = sAct[wrp][k8];
            u64 fp2 = sAct[wrp][k8 + 8];
            u64 gp2 = sAct[wrp][k8 + 16];
            u64 op2 = sAct[wrp][k8 + 24];

            c2 = ffma2(fp2, c2, fmul2(ip2, gp2));

            float dlo, dhi; upk2(c2, dlo, dhi);
            float ds = (lane & 8) ? dhi : dlo;
            float tD = tanh_acc(ds);
            float ulo = __shfl_sync(0xffffffffu, tD, k8);
            float uhi = __shfl_sync(0xffffffffu, tD, k8p8);
            u64 hq = fmul2(op2, pk2(ulo, uhi));

            if (lane < 8) sH2[wrp][lane] = hq;
            __syncwarp();
            {
                const ulonglong2* p = (const ulonglong2*)&sH2[wrp][0];
                ulonglong2 v0 = p[0], v1 = p[1], v2 = p[2], v3 = p[3];
                h2v[0] = v0.x; h2v[1] = v0.y; h2v[2] = v1.x; h2v[3] = v1.y;
                h2v[4] = v2.x; h2v[5] = v2.y; h2v[6] = v3.x; h2v[7] = v3.y;
            }
        }
    }

    // ======== FC: out[b, m] = sum_k W_fc[m,k] * h2[k] + b_fc[m] ========
    if (lane < 4) {
        float bf = b_fc[lane];
        u64 acc = pk2(bf, bf);
#pragma unroll
        for (int k = 0; k < HH; k++) {
            float w = W_fc[lane * HH + k];
            acc = ffma2(pk2(w, w), h2v[k], acc);
        }
        float o0, o1; upk2(acc, o0, o1);
        out[b0 * 4 + lane] = o0;
        out[b1 * 4 + lane] = o1;
    }
}

extern "C" void kernel_launch(void* const* d_in, const int* in_sizes, int n_in,
                              void* d_out, int out_size)
{
    const float* x     = (const float*)d_in[0];
    const float* W_ih1 = (const float*)d_in[1];
    const float* W_hh1 = (const float*)d_in[2];
    const float* b_ih1 = (const float*)d_in[3];
    const float* b_hh1 = (const float*)d_in[4];
    const float* W_ih2 = (const float*)d_in[5];
    const float* W_hh2 = (const float*)d_in[6];
    const float* b_ih2 = (const float*)d_in[7];
    const float* b_hh2 = (const float*)d_in[8];
    const float* W_fc  = (const float*)d_in[9];
    const float* b_fc  = (const float*)d_in[10];
    float* out = (float*)d_out;

    int B = in_sizes[0] / TT;                  // 4096
    int warps  = (B + 1) / 2;                  // 2 batch elements per warp
    int blocks = (warps + WPB - 1) / WPB;      // 1024 blocks of 64 threads

    lstm2_kernel<<<blocks, NTHR>>>(x, W_ih1, W_hh1, b_ih1, b_hh1,
                                   W_ih2, W_hh2, b_ih2, b_hh2,
                                   W_fc, b_fc, out, B);
}

// round 6
// speedup vs baseline: 1.2910x; 1.2910x over previous
#include <cuda_runtime.h>

typedef unsigned long long u64;

#define TT 512          // sequence length
#define HH 8            // hidden size

#define L2E 1.4426950408889634f

// ---- packed f32x2 helpers (Blackwell packed fp32 math) ----
static __device__ __forceinline__ u64 pk2(float lo, float hi) {
    u64 r; asm("mov.b64 %0, {%1,%2};" : "=l"(r) : "f"(lo), "f"(hi)); return r;
}
static __device__ __forceinline__ void upk2(u64 v, float& lo, float& hi) {
    asm("mov.b64 {%0,%1}, %2;" : "=f"(lo), "=f"(hi) : "l"(v));
}
static __device__ __forceinline__ u64 ffma2(u64 a, u64 b, u64 c) {
    u64 d; asm("fma.rn.f32x2 %0,%1,%2,%3;" : "=l"(d) : "l"(a), "l"(b), "l"(c)); return d;
}
static __device__ __forceinline__ u64 fmul2(u64 a, u64 b) {
    u64 d; asm("mul.rn.f32x2 %0,%1,%2;" : "=l"(d) : "l"(a), "l"(b)); return d;
}
static __device__ __forceinline__ u64 fadd2(u64 a, u64 b) {
    u64 d; asm("add.rn.f32x2 %0,%1,%2;" : "=l"(d) : "l"(a), "l"(b)); return d;
}
static __device__ __forceinline__ float ex2f(float x) {
    float y; asm("ex2.approx.f32 %0,%1;" : "=f"(y) : "f"(x)); return y;
}
static __device__ __forceinline__ float rcpf(float x) {
    float y; asm("rcp.approx.f32 %0,%1;" : "=f"(y) : "f"(x)); return y;
}
// segment-relative shuffles (width=16: source lane is a segment-relative
// literal, no base+lane ALU math)
static __device__ __forceinline__ u64 shfl64_g16(u64 v, int src) {
    return __shfl_sync(0xffffffffu, v, src, 16);
}
static __device__ __forceinline__ float shflf_g16(float v, int src) {
    return __shfl_sync(0xffffffffu, v, src, 16);
}
static __device__ __forceinline__ u64 bfly64(u64 v, int m) {
    return __shfl_xor_sync(0xffffffffu, v, m);
}

// Activation of a packed pair. Input g is the PRE-SCALED pre-activation:
//   sigmoid lanes: g = -z*log2e  -> sigma(z) = rcp(1 + 2^g)          (kA=+1, kB=0)
//   tanh lanes:    g = 2z*log2e  -> tanh(z)  = 1 - 2*rcp(1 + 2^g)    (kA=-2, kB=1)
// One MUFU.RCP serves BOTH packed halves via reciprocal-of-product.
// This exact formulation measured rel_err = 1.3e-7 end-to-end in Round 1.
static __device__ __forceinline__ u64 act_pair(u64 g, float kA, float kB) {
    float a, b; upk2(g, a, b);
    a = fminf(a, 60.f);            // keep d0*d1 finite (no fp32 overflow)
    b = fminf(b, 60.f);
    float d0 = 1.f + ex2f(a);
    float d1 = 1.f + ex2f(b);
    float r  = rcpf(d0 * d1);
    float r0 = r * d1;             // = 1/d0
    float r1 = r * d0;             // = 1/d1
    return pk2(fmaf(kA, r0, kB), fmaf(kA, r1, kB));
}

// packed tanh(c): tanh(z) = 1 - 2/(1 + 2^{2z*log2e}), shared-rcp trick
static __device__ __forceinline__ u64 tanh2(u64 c) {
    float a, b; upk2(c, a, b);
    a = fminf(a * (2.f * L2E), 60.f);
    b = fminf(b * (2.f * L2E), 60.f);
    float d0 = 1.f + ex2f(a);
    float d1 = 1.f + ex2f(b);
    float r  = rcpf(d0 * d1);
    return pk2(fmaf(-2.f, r * d1, 1.f), fmaf(-2.f, r * d0, 1.f));
}

// Layout: 1 warp/block. Warp = 2 independent groups of 16 lanes; each group =
// 2 batch elements packed in the f32x2 halves. Within a group, lane s (0..15):
//   k = s&7 (hidden index). s<8: owns gate rows {k (i), k+8 (f)}.
//   s>=8:   owns gate rows {16+k (g), 24+k (o)}.
// c_k/h_k computed redundantly on both owning lanes after a bfly(8) exchange.
// Zero shared memory, zero __syncwarp in the hot loop.
__global__ void __launch_bounds__(32)
lstm2_kernel(const float* __restrict__ x,
             const float* __restrict__ W_ih1, const float* __restrict__ W_hh1,
             const float* __restrict__ b_ih1, const float* __restrict__ b_hh1,
             const float* __restrict__ W_ih2, const float* __restrict__ W_hh2,
             const float* __restrict__ b_ih2, const float* __restrict__ b_hh2,
             const float* __restrict__ W_fc,  const float* __restrict__ b_fc,
             float* __restrict__ out, int B)
{
    const int L    = threadIdx.x;
    const int grp  = L >> 4;          // group in warp: 0/1
    const int s    = L & 15;
    const int k    = s & 7;
    const bool hi  = (s >= 8);        // owns (g,o) rows

    const int b0 = blockIdx.x * 4 + grp * 2;   // group's batch pair
    const int b1 = b0 + 1;
    if (b1 >= B) return;

    // my two gate rows
    const int r0 = hi ? (16 + k) : k;     // i (sig) or g (tanh)
    const int r1 = r0 + 8;                // f (sig) or o (sig)

    const float pre0 = hi ? (2.f * L2E) : (-L2E);
    const float pre1 = -L2E;
    const float kA0  = hi ? -2.f : 1.f;
    const float kB0  = hi ?  1.f : 0.f;

    // ---- dup-packed, pre-scaled weights (registers) ----
    u64 wx0, wx1, bb0, bb1, cb0, cb1;
    {
        float a = W_ih1[r0] * pre0;  wx0 = pk2(a, a);
        float b = W_ih1[r1] * pre1;  wx1 = pk2(b, b);
        float c = (b_ih1[r0] + b_hh1[r0]) * pre0;  bb0 = pk2(c, c);
        float d = (b_ih1[r1] + b_hh1[r1]) * pre1;  bb1 = pk2(d, d);
        float e = (b_ih2[r0] + b_hh2[r0]) * pre0;  cb0 = pk2(e, e);
        float f = (b_ih2[r1] + b_hh2[r1]) * pre1;  cb1 = pk2(f, f);
    }
    u64 wh1a[HH], wh1b[HH], wi2a[HH], wi2b[HH], wh2a[HH], wh2b[HH];
#pragma unroll
    for (int j = 0; j < HH; j++) {
        float a = W_hh1[r0 * HH + j] * pre0;  wh1a[j] = pk2(a, a);
        float b = W_hh1[r1 * HH + j] * pre1;  wh1b[j] = pk2(b, b);
        float c = W_ih2[r0 * HH + j] * pre0;  wi2a[j] = pk2(c, c);
        float d = W_ih2[r1 * HH + j] * pre1;  wi2b[j] = pk2(d, d);
        float e = W_hh2[r0 * HH + j] * pre0;  wh2a[j] = pk2(e, e);
        float f = W_hh2[r1 * HH + j] * pre1;  wh2b[j] = pk2(f, f);
    }

    // ---- state ----
    const u64 z2 = pk2(0.f, 0.f);
    u64 h1v[HH], h2v[HH];
#pragma unroll
    for (int j = 0; j < HH; j++) { h1v[j] = z2; h2v[j] = z2; }
    u64 c1 = z2, c2 = z2;

    // x loader: lane covers batch (b0 + hi) at t-offset k within each chunk of 8
    const float* xrow = x + (size_t)(b0 + (hi ? 1 : 0)) * TT + k;

    // prefetch first chunk; each iteration loads the NEXT chunk at the top so
    // the LDG retires behind ~8 steps of compute (no exposed load latency)
    float xv = xrow[0];

    for (int tc = 0; tc < TT; tc += 8) {
        float xnext = (tc + 8 < TT) ? xrow[tc + 8] : 0.f;

#pragma unroll
        for (int u = 0; u < 8; u++) {
            // x for both batches of my group (lane u: b0's t, lane 8+u: b1's t)
            float x0 = shflf_g16(xv, u);
            float x1 = shflf_g16(xv, 8 + u);
            u64 xp = pk2(x0, x1);

            // ---------- LAYER 1: 2 gate rows (9-wide dots) ----------
            u64 e0 = ffma2(wx0, xp, bb0);
            u64 o0 = fmul2(wh1a[1], h1v[1]);
            u64 e1 = ffma2(wx1, xp, bb1);
            u64 o1 = fmul2(wh1b[1], h1v[1]);
            e0 = ffma2(wh1a[0], h1v[0], e0);  o0 = ffma2(wh1a[3], h1v[3], o0);
            e1 = ffma2(wh1b[0], h1v[0], e1);  o1 = ffma2(wh1b[3], h1v[3], o1);
            e0 = ffma2(wh1a[2], h1v[2], e0);  o0 = ffma2(wh1a[5], h1v[5], o0);
            e1 = ffma2(wh1b[2], h1v[2], e1);  o1 = ffma2(wh1b[5], h1v[5], o1);
            e0 = ffma2(wh1a[4], h1v[4], e0);  o0 = ffma2(wh1a[7], h1v[7], o0);
            e1 = ffma2(wh1b[4], h1v[4], e1);  o1 = ffma2(wh1b[7], h1v[7], o1);
            e0 = ffma2(wh1a[6], h1v[6], e0);
            e1 = ffma2(wh1b[6], h1v[6], e1);

            u64 a0 = act_pair(fadd2(e0, o0), kA0, kB0);   // i or g
            u64 a1 = act_pair(fadd2(e1, o1), 1.f, 0.f);   // f or o

            u64 y0 = bfly64(a0, 8);                        // partner's (g or i)
            u64 y1 = bfly64(a1, 8);                        // partner's (o or f)

            u64 ig = fmul2(a0, y0);                        // i*g (commutative)
            u64 fg = hi ? y1 : a1;                         // forget gate
            u64 og = hi ? a1 : y1;                         // output gate
            c1 = ffma2(fg, c1, ig);
            u64 hp = fmul2(og, tanh2(c1));                 // h1_k (both copies)

            // h1 broadcast within group (segment lane k' owns h1_{k'})
            h1v[0] = shfl64_g16(hp, 0);
            h1v[1] = shfl64_g16(hp, 1);
            h1v[2] = shfl64_g16(hp, 2);
            h1v[3] = shfl64_g16(hp, 3);
            h1v[4] = shfl64_g16(hp, 4);
            h1v[5] = shfl64_g16(hp, 5);
            h1v[6] = shfl64_g16(hp, 6);
            h1v[7] = shfl64_g16(hp, 7);

            // ---------- LAYER 2: 2 gate rows (16-wide dots) ----------
            e0 = ffma2(wi2a[0], h1v[0], cb0);
            o0 = fmul2(wi2a[1], h1v[1]);
            e1 = ffma2(wi2b[0], h1v[0], cb1);
            o1 = fmul2(wi2b[1], h1v[1]);
            e0 = ffma2(wi2a[2], h1v[2], e0);  o0 = ffma2(wi2a[3], h1v[3], o0);
            e1 = ffma2(wi2b[2], h1v[2], e1);  o1 = ffma2(wi2b[3], h1v[3], o1);
            e0 = ffma2(wi2a[4], h1v[4], e0);  o0 = ffma2(wi2a[5], h1v[5], o0);
            e1 = ffma2(wi2b[4], h1v[4], e1);  o1 = ffma2(wi2b[5], h1v[5], o1);
            e0 = ffma2(wi2a[6], h1v[6], e0);  o0 = ffma2(wi2a[7], h1v[7], o0);
            e1 = ffma2(wi2b[6], h1v[6], e1);  o1 = ffma2(wi2b[7], h1v[7], o1);
            e0 = ffma2(wh2a[0], h2v[0], e0);  o0 = ffma2(wh2a[1], h2v[1], o0);
            e1 = ffma2(wh2b[0], h2v[0], e1);  o1 = ffma2(wh2b[1], h2v[1], o1);
            e0 = ffma2(wh2a[2], h2v[2], e0);  o0 = ffma2(wh2a[3], h2v[3], o0);
            e1 = ffma2(wh2b[2], h2v[2], e1);  o1 = ffma2(wh2b[3], h2v[3], o1);
            e0 = ffma2(wh2a[4], h2v[4], e0);  o0 = ffma2(wh2a[5], h2v[5], o0);
            e1 = ffma2(wh2b[4], h2v[4], e1);  o1 = ffma2(wh2b[5], h2v[5], o1);
            e0 = ffma2(wh2a[6], h2v[6], e0);  o0 = ffma2(wh2a[7], h2v[7], o0);
            e1 = ffma2(wh2b[6], h2v[6], e1);  o1 = ffma2(wh2b[7], h2v[7], o1);

            a0 = act_pair(fadd2(e0, o0), kA0, kB0);
            a1 = act_pair(fadd2(e1, o1), 1.f, 0.f);

            y0 = bfly64(a0, 8);
            y1 = bfly64(a1, 8);

            ig = fmul2(a0, y0);
            fg = hi ? y1 : a1;
            og = hi ? a1 : y1;
            c2 = ffma2(fg, c2, ig);
            u64 hq = fmul2(og, tanh2(c2));

            h2v[0] = shfl64_g16(hq, 0);
            h2v[1] = shfl64_g16(hq, 1);
            h2v[2] = shfl64_g16(hq, 2);
            h2v[3] = shfl64_g16(hq, 3);
            h2v[4] = shfl64_g16(hq, 4);
            h2v[5] = shfl64_g16(hq, 5);
            h2v[6] = shfl64_g16(hq, 6);
            h2v[7] = shfl64_g16(hq, 7);
        }

        xv = xnext;
    }

    // ======== FC: out[b, m] = sum_j W_fc[m,j] * h2[j] + b_fc[m] ========
    if (s < 4) {
        float bf = b_fc[s];
        u64 acc = pk2(bf, bf);
#pragma unroll
        for (int j = 0; j < HH; j++) {
            float w = W_fc[s * HH + j];
            acc = ffma2(pk2(w, w), h2v[j], acc);
        }
        float q0, q1; upk2(acc, q0, q1);
        out[b0 * 4 + s] = q0;
        out[b1 * 4 + s] = q1;
    }
}

extern "C" void kernel_launch(void* const* d_in, const int* in_sizes, int n_in,
                              void* d_out, int out_size)
{
    const float* x     = (const float*)d_in[0];
    const float* W_ih1 = (const float*)d_in[1];
    const float* W_hh1 = (const float*)d_in[2];
    const float* b_ih1 = (const float*)d_in[3];
    const float* b_hh1 = (const float*)d_in[4];
    const float* W_ih2 = (const float*)d_in[5];
    const float* W_hh2 = (const float*)d_in[6];
    const float* b_ih2 = (const float*)d_in[7];
    const float* b_hh2 = (const float*)d_in[8];
    const float* W_fc  = (const float*)d_in[9];
    const float* b_fc  = (const float*)d_in[10];
    float* out = (float*)d_out;

    int B = in_sizes[0] / TT;              // 4096
    int blocks = (B + 3) / 4;              // 4 batch elements per 1-warp block

    lstm2_kernel<<<blocks, 32>>>(x, W_ih1, W_hh1, b_ih1, b_hh1,
                                 W_ih2, W_hh2, b_ih2, b_hh2,
                                 W_fc, b_fc, out, B);
}

// round 8
// speedup vs baseline: 2.0005x; 1.5495x over previous
#include <cuda_runtime.h>

typedef unsigned long long u64;

#define TT 512          // sequence length
#define HH 8            // hidden size

// ---- packed f32x2 helpers (Blackwell packed fp32 math) ----
static __device__ __forceinline__ u64 pk2(float lo, float hi) {
    u64 r; asm("mov.b64 %0, {%1,%2};" : "=l"(r) : "f"(lo), "f"(hi)); return r;
}
static __device__ __forceinline__ void upk2(u64 v, float& lo, float& hi) {
    asm("mov.b64 {%0,%1}, %2;" : "=f"(lo), "=f"(hi) : "l"(v));
}
static __device__ __forceinline__ u64 ffma2(u64 a, u64 b, u64 c) {
    u64 d; asm("fma.rn.f32x2 %0,%1,%2,%3;" : "=l"(d) : "l"(a), "l"(b), "l"(c)); return d;
}
static __device__ __forceinline__ u64 fmul2(u64 a, u64 b) {
    u64 d; asm("mul.rn.f32x2 %0,%1,%2;" : "=l"(d) : "l"(a), "l"(b)); return d;
}
static __device__ __forceinline__ u64 fadd2(u64 a, u64 b) {
    u64 d; asm("add.rn.f32x2 %0,%1,%2;" : "=l"(d) : "l"(a), "l"(b)); return d;
}
static __device__ __forceinline__ float tanhap(float x) {
    float y; asm("tanh.approx.f32 %0,%1;" : "=f"(y) : "f"(x)); return y;
}
// segment-relative shuffles (width=16: source lane is a segment-relative literal)
static __device__ __forceinline__ u64 shfl64_g16(u64 v, int src) {
    return __shfl_sync(0xffffffffu, v, src, 16);
}
static __device__ __forceinline__ float shflf_g16(float v, int src) {
    return __shfl_sync(0xffffffffu, v, src, 16);
}
static __device__ __forceinline__ u64 bfly64(u64 v, int m) {
    return __shfl_xor_sync(0xffffffffu, v, m);
}

// Packed activation via MUFU.TANH.
//   sigmoid rows: weights pre-scaled by 0.5 -> sigma(z) = 0.5*tanh(z/2)+0.5  (kA=kB=0.5)
//   tanh row:     no pre-scale             -> tanh(z)                        (kA=1, kB=0)
static __device__ __forceinline__ u64 act_pair(u64 g, float kA, float kB) {
    float a, b; upk2(g, a, b);
    return pk2(fmaf(kA, tanhap(a), kB), fmaf(kA, tanhap(b), kB));
}
// packed tanh
static __device__ __forceinline__ u64 tanh2(u64 c) {
    float a, b; upk2(c, a, b);
    return pk2(tanhap(a), tanhap(b));
}

// Layout: 1 warp/block. Warp = 2 independent groups of 16 lanes; each group =
// 2 batch elements packed in the f32x2 halves. Within a group, lane s (0..15):
//   k = s&7 (hidden index). s<8: owns gate rows {k (i), k+8 (f)}.
//   s>=8:   owns gate rows {16+k (g), 24+k (o)}.
// c_k/h_k computed redundantly on both owning lanes after a bfly(8) exchange.
// Zero shared memory, zero __syncwarp in the hot loop.
__global__ void __launch_bounds__(32)
lstm2_kernel(const float* __restrict__ x,
             const float* __restrict__ W_ih1, const float* __restrict__ W_hh1,
             const float* __restrict__ b_ih1, const float* __restrict__ b_hh1,
             const float* __restrict__ W_ih2, const float* __restrict__ W_hh2,
             const float* __restrict__ b_ih2, const float* __restrict__ b_hh2,
             const float* __restrict__ W_fc,  const float* __restrict__ b_fc,
             float* __restrict__ out, int B)
{
    const int L    = threadIdx.x;
    const int grp  = L >> 4;          // group in warp: 0/1
    const int s    = L & 15;
    const int k    = s & 7;
    const bool hi  = (s >= 8);        // owns (g,o) rows

    const int b0 = blockIdx.x * 4 + grp * 2;   // group's batch pair
    const int b1 = b0 + 1;
    if (b1 >= B) return;

    // my two gate rows
    const int r0 = hi ? (16 + k) : k;     // i (sig) or g (tanh)
    const int r1 = r0 + 8;                // f (sig) or o (sig)

    // pre-scale: sigmoid rows 0.5 (tanh half-angle), g row 1.0
    const float pre0 = hi ? 1.0f : 0.5f;
    const float pre1 = 0.5f;
    const float kA0  = hi ? 1.0f : 0.5f;
    const float kB0  = hi ? 0.0f : 0.5f;

    // ---- dup-packed, pre-scaled weights (registers) ----
    u64 wx0, wx1, bb0, bb1, cb0, cb1;
    {
        float a = W_ih1[r0] * pre0;  wx0 = pk2(a, a);
        float b = W_ih1[r1] * pre1;  wx1 = pk2(b, b);
        float c = (b_ih1[r0] + b_hh1[r0]) * pre0;  bb0 = pk2(c, c);
        float d = (b_ih1[r1] + b_hh1[r1]) * pre1;  bb1 = pk2(d, d);
        float e = (b_ih2[r0] + b_hh2[r0]) * pre0;  cb0 = pk2(e, e);
        float f = (b_ih2[r1] + b_hh2[r1]) * pre1;  cb1 = pk2(f, f);
    }
    u64 wh1a[HH], wh1b[HH], wi2a[HH], wi2b[HH], wh2a[HH], wh2b[HH];
#pragma unroll
    for (int j = 0; j < HH; j++) {
        float a = W_hh1[r0 * HH + j] * pre0;  wh1a[j] = pk2(a, a);
        float b = W_hh1[r1 * HH + j] * pre1;  wh1b[j] = pk2(b, b);
        float c = W_ih2[r0 * HH + j] * pre0;  wi2a[j] = pk2(c, c);
        float d = W_ih2[r1 * HH + j] * pre1;  wi2b[j] = pk2(d, d);
        float e = W_hh2[r0 * HH + j] * pre0;  wh2a[j] = pk2(e, e);
        float f = W_hh2[r1 * HH + j] * pre1;  wh2b[j] = pk2(f, f);
    }

    // ---- state ----
    const u64 z2 = pk2(0.f, 0.f);
    u64 h1v[HH], h2v[HH];
#pragma unroll
    for (int j = 0; j < HH; j++) { h1v[j] = z2; h2v[j] = z2; }
    u64 c1 = z2, c2 = z2;

    // x loader: lane covers batch (b0 + hi) at t-offset k within each chunk of 8
    const float* xrow = x + (size_t)(b0 + (hi ? 1 : 0)) * TT + k;

    // prefetch: load next chunk at the top so the LDG retires behind ~8 steps
    float xv = xrow[0];

    for (int tc = 0; tc < TT; tc += 8) {
        float xnext = (tc + 8 < TT) ? xrow[tc + 8] : 0.f;

#pragma unroll
        for (int u = 0; u < 8; u++) {
            // x for both batches of my group (lane u: b0's t, lane 8+u: b1's t)
            float x0 = shflf_g16(xv, u);
            float x1 = shflf_g16(xv, 8 + u);
            u64 xp = pk2(x0, x1);

            // ---------- LAYER 1: 2 gate rows (9-wide dots) ----------
            u64 e0 = ffma2(wx0, xp, bb0);
            u64 o0 = fmul2(wh1a[1], h1v[1]);
            u64 e1 = ffma2(wx1, xp, bb1);
            u64 o1 = fmul2(wh1b[1], h1v[1]);
            e0 = ffma2(wh1a[0], h1v[0], e0);  o0 = ffma2(wh1a[3], h1v[3], o0);
            e1 = ffma2(wh1b[0], h1v[0], e1);  o1 = ffma2(wh1b[3], h1v[3], o1);
            e0 = ffma2(wh1a[2], h1v[2], e0);  o0 = ffma2(wh1a[5], h1v[5], o0);
            e1 = ffma2(wh1b[2], h1v[2], e1);  o1 = ffma2(wh1b[5], h1v[5], o1);
            e0 = ffma2(wh1a[4], h1v[4], e0);  o0 = ffma2(wh1a[7], h1v[7], o0);
            e1 = ffma2(wh1b[4], h1v[4], e1);  o1 = ffma2(wh1b[7], h1v[7], o1);
            e0 = ffma2(wh1a[6], h1v[6], e0);
            e1 = ffma2(wh1b[6], h1v[6], e1);

            u64 a0 = act_pair(fadd2(e0, o0), kA0, kB0);   // i or g
            u64 a1 = act_pair(fadd2(e1, o1), 0.5f, 0.5f); // f or o

            u64 y0 = bfly64(a0, 8);                        // partner's (g or i)
            u64 y1 = bfly64(a1, 8);                        // partner's (o or f)

            u64 ig = fmul2(a0, y0);                        // i*g (commutative)
            u64 fg = hi ? y1 : a1;                         // forget gate
            u64 og = hi ? a1 : y1;                         // output gate
            c1 = ffma2(fg, c1, ig);
            u64 hp = fmul2(og, tanh2(c1));                 // h1_k (both copies)

            // h1 broadcast within group (segment lane k' owns h1_{k'})
            h1v[0] = shfl64_g16(hp, 0);
            h1v[1] = shfl64_g16(hp, 1);
            h1v[2] = shfl64_g16(hp, 2);
            h1v[3] = shfl64_g16(hp, 3);
            h1v[4] = shfl64_g16(hp, 4);
            h1v[5] = shfl64_g16(hp, 5);
            h1v[6] = shfl64_g16(hp, 6);
            h1v[7] = shfl64_g16(hp, 7);

            // ---------- LAYER 2: 2 gate rows (16-wide dots) ----------
            e0 = ffma2(wi2a[0], h1v[0], cb0);
            o0 = fmul2(wi2a[1], h1v[1]);
            e1 = ffma2(wi2b[0], h1v[0], cb1);
            o1 = fmul2(wi2b[1], h1v[1]);
            e0 = ffma2(wi2a[2], h1v[2], e0);  o0 = ffma2(wi2a[3], h1v[3], o0);
            e1 = ffma2(wi2b[2], h1v[2], e1);  o1 = ffma2(wi2b[3], h1v[3], o1);
            e0 = ffma2(wi2a[4], h1v[4], e0);  o0 = ffma2(wi2a[5], h1v[5], o0);
            e1 = ffma2(wi2b[4], h1v[4], e1);  o1 = ffma2(wi2b[5], h1v[5], o1);
            e0 = ffma2(wi2a[6], h1v[6], e0);  o0 = ffma2(wi2a[7], h1v[7], o0);
            e1 = ffma2(wi2b[6], h1v[6], e1);  o1 = ffma2(wi2b[7], h1v[7], o1);
            e0 = ffma2(wh2a[0], h2v[0], e0);  o0 = ffma2(wh2a[1], h2v[1], o0);
            e1 = ffma2(wh2b[0], h2v[0], e1);  o1 = ffma2(wh2b[1], h2v[1], o1);
            e0 = ffma2(wh2a[2], h2v[2], e0);  o0 = ffma2(wh2a[3], h2v[3], o0);
            e1 = ffma2(wh2b[2], h2v[2], e1);  o1 = ffma2(wh2b[3], h2v[3], o1);
            e0 = ffma2(wh2a[4], h2v[4], e0);  o0 = ffma2(wh2a[5], h2v[5], o0);
            e1 = ffma2(wh2b[4], h2v[4], e1);  o1 = ffma2(wh2b[5], h2v[5], o1);
            e0 = ffma2(wh2a[6], h2v[6], e0);  o0 = ffma2(wh2a[7], h2v[7], o0);
            e1 = ffma2(wh2b[6], h2v[6], e1);  o1 = ffma2(wh2b[7], h2v[7], o1);

            a0 = act_pair(fadd2(e0, o0), kA0, kB0);
            a1 = act_pair(fadd2(e1, o1), 0.5f, 0.5f);

            y0 = bfly64(a0, 8);
            y1 = bfly64(a1, 8);

            ig = fmul2(a0, y0);
            fg = hi ? y1 : a1;
            og = hi ? a1 : y1;
            c2 = ffma2(fg, c2, ig);
            u64 hq = fmul2(og, tanh2(c2));

            h2v[0] = shfl64_g16(hq, 0);
            h2v[1] = shfl64_g16(hq, 1);
            h2v[2] = shfl64_g16(hq, 2);
            h2v[3] = shfl64_g16(hq, 3);
            h2v[4] = shfl64_g16(hq, 4);
            h2v[5] = shfl64_g16(hq, 5);
            h2v[6] = shfl64_g16(hq, 6);
            h2v[7] = shfl64_g16(hq, 7);
        }

        xv = xnext;
    }

    // ======== FC: out[b, m] = sum_j W_fc[m,j] * h2[j] + b_fc[m] ========
    if (s < 4) {
        float bf = b_fc[s];
        u64 acc = pk2(bf, bf);
#pragma unroll
        for (int j = 0; j < HH; j++) {
            float w = W_fc[s * HH + j];
            acc = ffma2(pk2(w, w), h2v[j], acc);
        }
        float q0, q1; upk2(acc, q0, q1);
        out[b0 * 4 + s] = q0;
        out[b1 * 4 + s] = q1;
    }
}

extern "C" void kernel_launch(void* const* d_in, const int* in_sizes, int n_in,
                              void* d_out, int out_size)
{
    const float* x     = (const float*)d_in[0];
    const float* W_ih1 = (const float*)d_in[1];
    const float* W_hh1 = (const float*)d_in[2];
    const float* b_ih1 = (const float*)d_in[3];
    const float* b_hh1 = (const float*)d_in[4];
    const float* W_ih2 = (const float*)d_in[5];
    const float* W_hh2 = (const float*)d_in[6];
    const float* b_ih2 = (const float*)d_in[7];
    const float* b_hh2 = (const float*)d_in[8];
    const float* W_fc  = (const float*)d_in[9];
    const float* b_fc  = (const float*)d_in[10];
    float* out = (float*)d_out;

    int B = in_sizes[0] / TT;              // 4096
    int blocks = (B + 3) / 4;              // 4 batch elements per 1-warp block

    lstm2_kernel<<<blocks, 32>>>(x, W_ih1, W_hh1, b_ih1, b_hh1,
                                 W_ih2, W_hh2, b_ih2, b_hh2,
                                 W_fc, b_fc, out, B);
}